// round 8
// baseline (speedup 1.0000x reference)
#include <cuda_runtime.h>
#include <cstdint>

#define N_ 50000
#define K_ 32
#define D_ 128
#define EPS_ 1e-12f
#define WARPS_PER_BLOCK 8
#define THREADS_ (WARPS_PER_BLOCK * 32)
#define NBLOCKS_ ((N_ + WARPS_PER_BLOCK - 1) / WARPS_PER_BLOCK)   // 6250

#define QS_    1398101.25f          // 2^23 / 6
#define INV_S2 (1.0f / (QS_ * QS_))

__device__ int16_t  g_hi[(size_t)N_ * D_];   // 12.8 MB
__device__ uint8_t  g_lo[(size_t)N_ * D_];   // 6.4 MB
__device__ double   g_block_partials[NBLOCKS_];
__device__ unsigned g_ticket = 0;            // returns to 0 each run (graph-replay safe)

// Quantize the embedding table to 24-bit fixed point: v = round(y*QS), hi=v>>8, lo=v&255.
__global__ __launch_bounds__(256)
void snl_quant_kernel(const float* __restrict__ emb) {
    const int idx = blockIdx.x * 256 + threadIdx.x;       // over N_*D_/4 = 1.6M
    const float4 y = reinterpret_cast<const float4*>(emb)[idx];

    int v0 = __float2int_rn(y.x * QS_);
    int v1 = __float2int_rn(y.y * QS_);
    int v2 = __float2int_rn(y.z * QS_);
    int v3 = __float2int_rn(y.w * QS_);
    v0 = max(-8388608, min(8388607, v0));
    v1 = max(-8388608, min(8388607, v1));
    v2 = max(-8388608, min(8388607, v2));
    v3 = max(-8388608, min(8388607, v3));

    short4 h;
    h.x = (short)(v0 >> 8); h.y = (short)(v1 >> 8);
    h.z = (short)(v2 >> 8); h.w = (short)(v3 >> 8);
    uchar4 l;
    l.x = (unsigned char)(v0 & 255); l.y = (unsigned char)(v1 & 255);
    l.z = (unsigned char)(v2 & 255); l.w = (unsigned char)(v3 & 255);

    reinterpret_cast<short4*>(g_hi)[idx] = h;
    reinterpret_cast<uchar4*>(g_lo)[idx] = l;
}

__global__ __launch_bounds__(THREADS_, 6)
void snl_main_kernel(const float* __restrict__ emb,
                     const float* __restrict__ p,
                     const int* __restrict__ anchor,
                     float* __restrict__ out /* [0]=loss, [1..]=q */) {
    __shared__ double loss_s[WARPS_PER_BLOCK];
    __shared__ double red_s[THREADS_];
    __shared__ bool   is_last;

    const int warp = threadIdx.x >> 5;
    const int lane = threadIdx.x & 31;
    const int i = blockIdx.x * WARPS_PER_BLOCK + warp;   // 6250*8 == 50000 exactly
    float* __restrict__ out_q = out + 1;

    // yi (exact fp32): lane t holds elements [4t, 4t+4); pre-scale into quantized domain.
    const float4 a0 = reinterpret_cast<const float4*>(emb + (size_t)i * D_)[lane];
    const float4 a = make_float4(a0.x * QS_, a0.y * QS_, a0.z * QS_, a0.w * QS_);

    int j_mine = anchor[(size_t)i * K_ + lane];
    j_mine = max(0, min(j_mine, N_ - 1));                // defensive clamp

    const bool hi16 = (lane & 16) != 0;
    const bool hi8  = (lane & 8) != 0;

    // per-anchor partial in scaled domain: lane t covers dims 4t..4t+3
    auto partial = [&](int jr) -> float {
        const short4 h = reinterpret_cast<const short4*>(g_hi + (size_t)jr * D_)[lane];
        const uchar4 l = reinterpret_cast<const uchar4*>(g_lo + (size_t)jr * D_)[lane];
        const float bx = (float)(h.x * 256 + (int)l.x);
        const float by = (float)(h.y * 256 + (int)l.y);
        const float bz = (float)(h.z * 256 + (int)l.z);
        const float bw = (float)(h.w * 256 + (int)l.w);
        const float dx = a.x - bx, dy = a.y - by, dz = a.z - bz, dw = a.w - bw;
        float pr = dx * dx;
        pr = fmaf(dy, dy, pr);
        pr = fmaf(dz, dz, pr);
        pr = fmaf(dw, dw, pr);
        return pr;
    };

    // 4-way folded partials: w[g] covers anchors 4g..4g+3 (8 live registers).
    float w[K_ / 4];
    #pragma unroll
    for (int g = 0; g < K_ / 4; g++) {
        const int jr0 = __shfl_sync(0xffffffffu, j_mine, 4 * g);
        const int jr1 = __shfl_sync(0xffffffffu, j_mine, 4 * g + 1);
        const int jr2 = __shfl_sync(0xffffffffu, j_mine, 4 * g + 2);
        const int jr3 = __shfl_sync(0xffffffffu, j_mine, 4 * g + 3);
        const float p0 = partial(jr0);
        const float p1 = partial(jr1);
        const float p2 = partial(jr2);
        const float p3 = partial(jr3);

        float s01 = hi16 ? p0 : p1;
        float u01 = (hi16 ? p1 : p0) + __shfl_xor_sync(0xffffffffu, s01, 16);
        float s23 = hi16 ? p2 : p3;
        float u23 = (hi16 ? p3 : p2) + __shfl_xor_sync(0xffffffffu, s23, 16);
        float s8 = hi8 ? u01 : u23;
        w[g] = (hi8 ? u23 : u01) + __shfl_xor_sync(0xffffffffu, s8, 8);
    }

    // Recursive halving on 8 values: 7 shuffles; lane l ends with anchor a(l).
    #pragma unroll
    for (int s = 4; s >= 1; s >>= 1) {
        const bool upper = (lane & s) != 0;
        #pragma unroll
        for (int k = 0; k < s; k++) {
            const float send = upper ? w[k] : w[k + s];
            const float recv = __shfl_xor_sync(0xffffffffu, send, s);
            w[k] = (upper ? w[k + s] : w[k]) + recv;
        }
    }
    const float myd2 = w[0] * INV_S2;   // back to real units
    const int acol = 4 * (lane & 7) + 2 * ((lane >> 3) & 1) + ((lane >> 4) & 1);

    // softmax over the 32 lanes
    const float sc = -myd2;
    float m = sc;
    #pragma unroll
    for (int o = 16; o; o >>= 1) m = fmaxf(m, __shfl_xor_sync(0xffffffffu, m, o));
    const float e = __expf(sc - m);
    float sum = e;
    #pragma unroll
    for (int o = 16; o; o >>= 1) sum += __shfl_xor_sync(0xffffffffu, sum, o);
    const float lse = m + __logf(sum);
    const float logq = sc - lse;
    const float q = __expf(logq);

    const float pv = p[(size_t)i * K_ + acol];
    out_q[(size_t)i * K_ + acol] = q;

    float contrib = pv * (__logf(pv + EPS_) - logq);
    #pragma unroll
    for (int o = 16; o; o >>= 1) contrib += __shfl_xor_sync(0xffffffffu, contrib, o);
    if (lane == 0) loss_s[warp] = (double)contrib;
    __syncthreads();

    if (threadIdx.x == 0) {
        double blk = 0.0;
        #pragma unroll
        for (int w2 = 0; w2 < WARPS_PER_BLOCK; w2++) blk += loss_s[w2];
        g_block_partials[blockIdx.x] = blk;
        __threadfence();
        unsigned t = atomicAdd(&g_ticket, 1u);
        is_last = (t == (unsigned)(NBLOCKS_ - 1));
    }
    __syncthreads();

    if (is_last) {
        __threadfence();
        double acc = 0.0;
        for (int b = threadIdx.x; b < NBLOCKS_; b += THREADS_)
            acc += g_block_partials[b];
        red_s[threadIdx.x] = acc;
        __syncthreads();
        #pragma unroll
        for (int o = THREADS_ / 2; o; o >>= 1) {
            if (threadIdx.x < o) red_s[threadIdx.x] += red_s[threadIdx.x + o];
            __syncthreads();
        }
        if (threadIdx.x == 0) {
            out[0] = (float)(red_s[0] / (double)N_);
            g_ticket = 0;
        }
    }
}

extern "C" void kernel_launch(void* const* d_in, const int* in_sizes, int n_in,
                              void* d_out, int out_size) {
    const float* emb    = (const float*)d_in[0];  // output_embedding [N, D] f32
    const float* p      = (const float*)d_in[1];  // input_similarity [N, K] f32
    const int*   anchor = (const int*)d_in[2];    // anchor_idx [N, K] int32
    float* out = (float*)d_out;                   // [0]=loss, [1..]=q row-major

    snl_quant_kernel<<<(N_ * D_ / 4 + 255) / 256, 256>>>(emb);
    snl_main_kernel<<<NBLOCKS_, THREADS_>>>(emb, p, anchor, out);
}

// round 9
// speedup vs baseline: 1.2926x; 1.2926x over previous
#include <cuda_runtime.h>
#include <cstdint>

#define N_ 50000
#define K_ 32
#define D_ 128
#define EPS_ 1e-12f
#define WARPS_PER_BLOCK 8
#define THREADS_ (WARPS_PER_BLOCK * 32)
#define NBLOCKS_ ((N_ + WARPS_PER_BLOCK - 1) / WARPS_PER_BLOCK)   // 6250

__device__ uint16_t g_hi[(size_t)N_ * D_];   // fp32 bits [31:16]  (12.8 MB)
__device__ uint8_t  g_lo[(size_t)N_ * D_];   // fp32 bits [15:8]   (6.4 MB)
__device__ double   g_block_partials[NBLOCKS_];
__device__ unsigned g_ticket = 0;            // returns to 0 each run (graph-replay safe)

// Round fp32 to 24 bits (15-bit mantissa) and split into hi16/lo8 bit planes.
// Integer add of 0x80 on the raw bits rounds the dropped byte (mantissa->exp
// carry is handled naturally by IEEE bit layout; |y| < 10 so no overflow).
__global__ __launch_bounds__(256)
void snl_quant_kernel(const float* __restrict__ emb) {
    const int idx = blockIdx.x * 256 + threadIdx.x;       // over N_*D_/4 = 1.6M
    const uint4 y = reinterpret_cast<const uint4*>(emb)[idx];

    const unsigned r0 = y.x + 0x80u, r1 = y.y + 0x80u;
    const unsigned r2 = y.z + 0x80u, r3 = y.w + 0x80u;

    ushort4 h;
    h.x = (unsigned short)(r0 >> 16); h.y = (unsigned short)(r1 >> 16);
    h.z = (unsigned short)(r2 >> 16); h.w = (unsigned short)(r3 >> 16);
    uchar4 l;
    l.x = (unsigned char)(r0 >> 8); l.y = (unsigned char)(r1 >> 8);
    l.z = (unsigned char)(r2 >> 8); l.w = (unsigned char)(r3 >> 8);

    reinterpret_cast<ushort4*>(g_hi)[idx] = h;
    reinterpret_cast<uchar4*>(g_lo)[idx] = l;
}

__global__ __launch_bounds__(THREADS_, 6)
void snl_main_kernel(const float* __restrict__ emb,
                     const float* __restrict__ p,
                     const int* __restrict__ anchor,
                     float* __restrict__ out /* [0]=loss, [1..]=q */) {
    __shared__ double loss_s[WARPS_PER_BLOCK];
    __shared__ double red_s[THREADS_];
    __shared__ bool   is_last;

    const int warp = threadIdx.x >> 5;
    const int lane = threadIdx.x & 31;
    const int i = blockIdx.x * WARPS_PER_BLOCK + warp;   // 6250*8 == 50000 exactly
    float* __restrict__ out_q = out + 1;

    // yi (exact fp32): lane t holds elements [4t, 4t+4)
    const float4 a = reinterpret_cast<const float4*>(emb + (size_t)i * D_)[lane];

    int j_mine = anchor[(size_t)i * K_ + lane];
    j_mine = max(0, min(j_mine, N_ - 1));                // defensive clamp

    const bool hi16 = (lane & 16) != 0;
    const bool hi8  = (lane & 8) != 0;

    // per-anchor partial: lane t covers dims 4t..4t+3.
    // b reconstructed from bit planes with one PRMT per element (no I2F!).
    auto partial = [&](int jr) -> float {
        const uint2    hw = *reinterpret_cast<const uint2*>(g_hi + (size_t)jr * D_ + 4 * lane);
        const unsigned lw = *reinterpret_cast<const unsigned*>(g_lo + (size_t)jr * D_ + 4 * lane);
        // fp32 bytes [b3 b2 b1 b0] = [hi.hiB, hi.loB, lo8, junk]
        const float bx = __uint_as_float(__byte_perm(hw.x, lw, 0x1044));
        const float by = __uint_as_float(__byte_perm(hw.x, lw, 0x3255));
        const float bz = __uint_as_float(__byte_perm(hw.y, lw, 0x1066));
        const float bw = __uint_as_float(__byte_perm(hw.y, lw, 0x3277));
        const float dx = a.x - bx, dy = a.y - by, dz = a.z - bz, dw = a.w - bw;
        float pr = dx * dx;
        pr = fmaf(dy, dy, pr);
        pr = fmaf(dz, dz, pr);
        pr = fmaf(dw, dw, pr);
        return pr;
    };

    // 4-way folded partials: w[g] covers anchors 4g..4g+3 (8 live registers).
    float w[K_ / 4];
    #pragma unroll
    for (int g = 0; g < K_ / 4; g++) {
        const int jr0 = __shfl_sync(0xffffffffu, j_mine, 4 * g);
        const int jr1 = __shfl_sync(0xffffffffu, j_mine, 4 * g + 1);
        const int jr2 = __shfl_sync(0xffffffffu, j_mine, 4 * g + 2);
        const int jr3 = __shfl_sync(0xffffffffu, j_mine, 4 * g + 3);
        const float p0 = partial(jr0);
        const float p1 = partial(jr1);
        const float p2 = partial(jr2);
        const float p3 = partial(jr3);

        float s01 = hi16 ? p0 : p1;
        float u01 = (hi16 ? p1 : p0) + __shfl_xor_sync(0xffffffffu, s01, 16);
        float s23 = hi16 ? p2 : p3;
        float u23 = (hi16 ? p3 : p2) + __shfl_xor_sync(0xffffffffu, s23, 16);
        float s8 = hi8 ? u01 : u23;
        w[g] = (hi8 ? u23 : u01) + __shfl_xor_sync(0xffffffffu, s8, 8);
    }

    // Recursive halving on 8 values: 7 shuffles; lane l ends with anchor a(l).
    #pragma unroll
    for (int s = 4; s >= 1; s >>= 1) {
        const bool upper = (lane & s) != 0;
        #pragma unroll
        for (int k = 0; k < s; k++) {
            const float send = upper ? w[k] : w[k + s];
            const float recv = __shfl_xor_sync(0xffffffffu, send, s);
            w[k] = (upper ? w[k + s] : w[k]) + recv;
        }
    }
    const float myd2 = w[0];
    const int acol = 4 * (lane & 7) + 2 * ((lane >> 3) & 1) + ((lane >> 4) & 1);

    // softmax over the 32 lanes
    const float sc = -myd2;
    float m = sc;
    #pragma unroll
    for (int o = 16; o; o >>= 1) m = fmaxf(m, __shfl_xor_sync(0xffffffffu, m, o));
    const float e = __expf(sc - m);
    float sum = e;
    #pragma unroll
    for (int o = 16; o; o >>= 1) sum += __shfl_xor_sync(0xffffffffu, sum, o);
    const float lse = m + __logf(sum);
    const float logq = sc - lse;
    const float q = __expf(logq);

    const float pv = p[(size_t)i * K_ + acol];
    out_q[(size_t)i * K_ + acol] = q;

    float contrib = pv * (__logf(pv + EPS_) - logq);
    #pragma unroll
    for (int o = 16; o; o >>= 1) contrib += __shfl_xor_sync(0xffffffffu, contrib, o);
    if (lane == 0) loss_s[warp] = (double)contrib;
    __syncthreads();

    if (threadIdx.x == 0) {
        double blk = 0.0;
        #pragma unroll
        for (int w2 = 0; w2 < WARPS_PER_BLOCK; w2++) blk += loss_s[w2];
        g_block_partials[blockIdx.x] = blk;
        __threadfence();
        unsigned t = atomicAdd(&g_ticket, 1u);
        is_last = (t == (unsigned)(NBLOCKS_ - 1));
    }
    __syncthreads();

    if (is_last) {
        __threadfence();
        double acc = 0.0;
        for (int b = threadIdx.x; b < NBLOCKS_; b += THREADS_)
            acc += g_block_partials[b];
        red_s[threadIdx.x] = acc;
        __syncthreads();
        #pragma unroll
        for (int o = THREADS_ / 2; o; o >>= 1) {
            if (threadIdx.x < o) red_s[threadIdx.x] += red_s[threadIdx.x + o];
            __syncthreads();
        }
        if (threadIdx.x == 0) {
            out[0] = (float)(red_s[0] / (double)N_);
            g_ticket = 0;
        }
    }
}

extern "C" void kernel_launch(void* const* d_in, const int* in_sizes, int n_in,
                              void* d_out, int out_size) {
    const float* emb    = (const float*)d_in[0];  // output_embedding [N, D] f32
    const float* p      = (const float*)d_in[1];  // input_similarity [N, K] f32
    const int*   anchor = (const int*)d_in[2];    // anchor_idx [N, K] int32
    float* out = (float*)d_out;                   // [0]=loss, [1..]=q row-major

    snl_quant_kernel<<<(N_ * D_ / 4 + 255) / 256, 256>>>(emb);
    snl_main_kernel<<<NBLOCKS_, THREADS_>>>(emb, p, anchor, out);
}